// round 6
// baseline (speedup 1.0000x reference)
#include <cuda_runtime.h>

#define N_NODES 40000
#define E_EDGES 640000
#define IN_CH   128
#define HID     256
#define OUT_CH  10
#define G_GR    64

// -------- device scratch (no allocs allowed; resolved in device code only) --------
__device__ float g_bufA[N_NODES * HID];   // ping
__device__ float g_bufB[N_NODES * HID];   // pong
__device__ float g_dis[N_NODES];          // rsqrt(deg) incl. self loop
__device__ int   g_ecnt[N_NODES];         // in-edge count (excl. self loop)
__device__ int   g_off[N_NODES + 1];      // CSR offsets (edges only)
__device__ int   g_cur[N_NODES];          // fill cursors
__device__ int   g_csr[E_EDGES];          // src node per dst-sorted edge
__device__ float g_pool[G_GR * HID];
__device__ float g_cnt[G_GR];
__device__ int   g_is32;                  // 1 if index buffers are int32, 0 if int64

__device__ __forceinline__ float* buf_sel(int i) { return i ? g_bufB : g_bufA; }

__device__ __forceinline__ int load_idx(const void* p, long i) {
    return g_is32 ? ((const int*)p)[i] : (int)((const long long*)p)[i];
}

// -------- dtype probe: read first 2048 words of edge_index as int64.
// int32 data read as int64 yields values >= 2^32 whenever the upper word != 0;
// genuine int64 indices are all in [0, N_NODES). Safe: 2048*8B << buffer size.
__global__ void detect_kernel(const void* ei) {
    int t = threadIdx.x;
    if (t == 0) g_is32 = 0;
    __syncthreads();
    const long long* p = (const long long*)ei;
    for (int i = t; i < 2048; i += blockDim.x) {
        long long v = p[i];
        if (v < 0 || v >= N_NODES) g_is32 = 1;
    }
}

// -------- init --------
__global__ void init_kernel() {
    int i = blockIdx.x * blockDim.x + threadIdx.x;
    if (i < N_NODES) g_ecnt[i] = 0;
    if (i < G_GR * HID) g_pool[i] = 0.f;
    if (i < G_GR) g_cnt[i] = 0.f;
}

// -------- count in-degree over dst --------
__global__ void count_kernel(const void* __restrict__ ei) {
    int e = blockIdx.x * blockDim.x + threadIdx.x;
    if (e < E_EDGES) {
        int d = load_idx(ei, (long)E_EDGES + e);
        atomicAdd(&g_ecnt[d], 1);
    }
}

// -------- single-block scan for CSR offsets --------
__global__ void scan_kernel() {
    __shared__ int wsum[32];
    __shared__ int carry_s;
    int t = threadIdx.x;
    int lane = t & 31, wid = t >> 5;
    if (t == 0) carry_s = 0;
    __syncthreads();
    for (int base = 0; base < N_NODES; base += 1024) {
        int v = (base + t < N_NODES) ? g_ecnt[base + t] : 0;
        int x = v;
        #pragma unroll
        for (int o = 1; o < 32; o <<= 1) {
            int y = __shfl_up_sync(0xffffffffu, x, o);
            if (lane >= o) x += y;
        }
        if (lane == 31) wsum[wid] = x;
        __syncthreads();
        if (wid == 0) {
            int s = wsum[lane];
            #pragma unroll
            for (int o = 1; o < 32; o <<= 1) {
                int y = __shfl_up_sync(0xffffffffu, s, o);
                if (lane >= o) s += y;
            }
            wsum[lane] = s;
        }
        __syncthreads();
        int incl = x + (wid > 0 ? wsum[wid - 1] : 0);
        if (base + t < N_NODES) g_off[base + t + 1] = carry_s + incl;
        __syncthreads();
        if (t == 1023) carry_s += incl;
        __syncthreads();
    }
    if (t == 0) g_off[0] = 0;
}

// -------- dis = rsqrt(deg incl self loop); cursor init --------
__global__ void dis_kernel() {
    int i = blockIdx.x * blockDim.x + threadIdx.x;
    if (i < N_NODES) {
        g_dis[i] = rsqrtf((float)(g_ecnt[i] + 1));
        g_cur[i] = g_off[i];
    }
}

// -------- fill CSR --------
__global__ void fill_kernel(const void* __restrict__ ei) {
    int e = blockIdx.x * blockDim.x + threadIdx.x;
    if (e < E_EDGES) {
        int s = load_idx(ei, e);
        int d = load_idx(ei, (long)E_EDGES + e);
        int pos = atomicAdd(&g_cur[d], 1);
        g_csr[pos] = s;
    }
}

// -------- SGEMM: C[M,Nc] = A[M,K] @ B[K,Nc], fp32, BM=64 BN=128 BK=16 --------
// A_ext != nullptr -> use it, else buf_sel(srcSel). C = buf_sel(dstSel).
__global__ __launch_bounds__(256)
void sgemm_kernel(const float* A_ext, int srcSel, int dstSel,
                  const float* __restrict__ B, int Nc, int K) {
    const int BM = 64, BN = 128, BK = 16;
    const float* A = A_ext ? A_ext : buf_sel(srcSel);
    float* C = buf_sel(dstSel);
    __shared__ float As[BK][BM];
    __shared__ float Bs[BK][BN];
    int tid = threadIdx.x;
    int tx = tid & 15, ty = tid >> 4;
    int row0 = blockIdx.y * BM, col0 = blockIdx.x * BN;

    float acc[4][8];
    #pragma unroll
    for (int m = 0; m < 4; m++)
        #pragma unroll
        for (int n = 0; n < 8; n++) acc[m][n] = 0.f;

    int arow = tid >> 2;          // 0..63
    int akq  = (tid & 3) * 4;     // k offset within BK (float4)
    int bk   = tid >> 4;          // 0..15
    int bn   = (tid & 15) * 4;    // 0..60

    for (int k0 = 0; k0 < K; k0 += BK) {
        float4 a4 = *(const float4*)(A + (long)(row0 + arow) * K + k0 + akq);
        As[akq + 0][arow] = a4.x;
        As[akq + 1][arow] = a4.y;
        As[akq + 2][arow] = a4.z;
        As[akq + 3][arow] = a4.w;
        float4 b4a = *(const float4*)(B + (long)(k0 + bk) * Nc + col0 + bn);
        float4 b4b = *(const float4*)(B + (long)(k0 + bk) * Nc + col0 + bn + 64);
        *(float4*)&Bs[bk][bn]      = b4a;
        *(float4*)&Bs[bk][bn + 64] = b4b;
        __syncthreads();
        #pragma unroll
        for (int k = 0; k < BK; k++) {
            float a[4];
            #pragma unroll
            for (int m = 0; m < 4; m++) a[m] = As[k][ty * 4 + m];
            float4 t0 = *(float4*)&Bs[k][tx * 8];
            float4 t1 = *(float4*)&Bs[k][tx * 8 + 4];
            float b[8] = {t0.x, t0.y, t0.z, t0.w, t1.x, t1.y, t1.z, t1.w};
            #pragma unroll
            for (int m = 0; m < 4; m++)
                #pragma unroll
                for (int n = 0; n < 8; n++) acc[m][n] = fmaf(a[m], b[n], acc[m][n]);
        }
        __syncthreads();
    }
    #pragma unroll
    for (int m = 0; m < 4; m++) {
        long r = row0 + ty * 4 + m;
        float4 o0 = make_float4(acc[m][0], acc[m][1], acc[m][2], acc[m][3]);
        float4 o1 = make_float4(acc[m][4], acc[m][5], acc[m][6], acc[m][7]);
        *(float4*)(C + r * Nc + col0 + tx * 8)     = o0;
        *(float4*)(C + r * Nc + col0 + tx * 8 + 4) = o1;
    }
}

// -------- aggregation: out = relu(self + sum_{e:dst=i} h[src]*dis[src]*dis[i] + b)
// 64-thread group per node (HID/4 = 64 float4 per thread-group)
__global__ __launch_bounds__(256)
void agg_kernel(int srcSel, int dstSel, const float* __restrict__ bias) {
    const float* hin = buf_sel(srcSel);
    float* hout = buf_sel(dstSel);
    int node = blockIdx.x * 4 + (threadIdx.x >> 6);
    int t = threadIdx.x & 63;
    const float4* h4 = (const float4*)hin;
    float di = g_dis[node];
    float4 v = h4[(long)node * 64 + t];
    float w0 = di * di;
    float4 acc = make_float4(v.x * w0, v.y * w0, v.z * w0, v.w * w0);
    int e = g_off[node], end = g_off[node + 1];
    for (; e + 1 < end; e += 2) {
        int s0 = g_csr[e], s1 = g_csr[e + 1];
        float ws0 = g_dis[s0] * di, ws1 = g_dis[s1] * di;
        float4 u0 = h4[(long)s0 * 64 + t];
        float4 u1 = h4[(long)s1 * 64 + t];
        acc.x += u0.x * ws0 + u1.x * ws1;
        acc.y += u0.y * ws0 + u1.y * ws1;
        acc.z += u0.z * ws0 + u1.z * ws1;
        acc.w += u0.w * ws0 + u1.w * ws1;
    }
    if (e < end) {
        int s0 = g_csr[e];
        float ws0 = g_dis[s0] * di;
        float4 u0 = h4[(long)s0 * 64 + t];
        acc.x += u0.x * ws0; acc.y += u0.y * ws0;
        acc.z += u0.z * ws0; acc.w += u0.w * ws0;
    }
    float4 b = ((const float4*)bias)[t];
    float4 o;
    o.x = fmaxf(acc.x + b.x, 0.f);
    o.y = fmaxf(acc.y + b.y, 0.f);
    o.z = fmaxf(acc.z + b.z, 0.f);
    o.w = fmaxf(acc.w + b.w, 0.f);
    ((float4*)hout)[(long)node * 64 + t] = o;
}

// -------- mean pool: exploit sorted batch, run-length accumulate + sparse atomics
__global__ __launch_bounds__(256)
void pool_kernel(int srcSel, const void* __restrict__ batch) {
    const float* h = buf_sel(srcSel);
    int base = blockIdx.x * 32;
    int c = threadIdx.x;           // one column per thread (HID == 256)
    float acc = 0.f, cacc = 0.f;
    int gprev = load_idx(batch, base);
    for (int r = 0; r < 32; r++) {
        int i = base + r;
        int g = load_idx(batch, i);
        if (g != gprev) {
            atomicAdd(&g_pool[gprev * HID + c], acc);
            if (c == 0) atomicAdd(&g_cnt[gprev], cacc);
            acc = 0.f; cacc = 0.f; gprev = g;
        }
        acc += h[(long)i * HID + c];
        cacc += 1.f;
    }
    atomicAdd(&g_pool[gprev * HID + c], acc);
    if (c == 0) atomicAdd(&g_cnt[gprev], cacc);
}

// -------- final linear head: [64,256] @ [256,10] + b --------
__global__ void final_kernel(const float* __restrict__ Wlin,
                             const float* __restrict__ blin,
                             float* __restrict__ out) {
    int t = threadIdx.x;
    if (t >= G_GR * OUT_CH) return;
    int g = t / OUT_CH, o = t % OUT_CH;
    float inv = 1.f / fmaxf(g_cnt[g], 1.f);
    float acc = 0.f;
    for (int c = 0; c < HID; c++)
        acc = fmaf(g_pool[g * HID + c] * inv, Wlin[c * OUT_CH + o], acc);
    out[t] = acc + blin[o];
}

extern "C" void kernel_launch(void* const* d_in, const int* in_sizes, int n_in,
                              void* d_out, int out_size) {
    const float* x     = (const float*)d_in[0];
    const void*  ei    = d_in[1];
    const void*  batch = d_in[2];
    const float* W1    = (const float*)d_in[3];
    const float* b1    = (const float*)d_in[4];
    const float* W2    = (const float*)d_in[5];
    const float* b2    = (const float*)d_in[6];
    const float* Wlin  = (const float*)d_in[7];
    const float* blin  = (const float*)d_in[8];
    float* out = (float*)d_out;

    // graph preprocessing
    detect_kernel<<<1, 256>>>(ei);
    init_kernel<<<(N_NODES + 255) / 256, 256>>>();
    count_kernel<<<(E_EDGES + 255) / 256, 256>>>(ei);
    scan_kernel<<<1, 1024>>>();
    dis_kernel<<<(N_NODES + 255) / 256, 256>>>();
    fill_kernel<<<(E_EDGES + 255) / 256, 256>>>(ei);

    // layer 1: h1 = x @ W1 -> bufA ; bufB = relu(agg(bufA) + b1)
    sgemm_kernel<<<dim3(HID / 128, N_NODES / 64), 256>>>(x, 0, 0, W1, HID, IN_CH);
    agg_kernel<<<N_NODES / 4, 256>>>(0, 1, b1);

    // layer 2: h2 = bufB @ W2 -> bufA ; bufB = relu(agg(bufA) + b2)
    sgemm_kernel<<<dim3(HID / 128, N_NODES / 64), 256>>>(nullptr, 1, 0, W2, HID, HID);
    agg_kernel<<<N_NODES / 4, 256>>>(0, 1, b2);

    // pool + head (reads bufB)
    pool_kernel<<<N_NODES / 32, 256>>>(1, batch);
    final_kernel<<<1, ((G_GR * OUT_CH + 31) / 32) * 32>>>(Wlin, blin, out);
}

// round 9
// speedup vs baseline: 1.0432x; 1.0432x over previous
#include <cuda_runtime.h>
#include <cstdint>

#define N_NODES 40000
#define E_EDGES 640000
#define IN_CH   128
#define HID     256
#define OUT_CH  10
#define G_GR    64
#define NBLK_SCAN 40   // ceil(40000/1024)

// packed 2-wide fp32 FMA (Blackwell f32x2 path; ptxas never auto-fuses this)
#define FMA_F32X2(d, a, b, c) \
    asm("fma.rn.f32x2 %0, %1, %2, %3;" : "=l"(d) : "l"(a), "l"(b), "l"(c))
#define PACK_F32X2(out, lo, hi) \
    asm("mov.b64 %0, {%1, %2};" : "=l"(out) : "f"(lo), "f"(hi))
#define UNPACK_F32X2(lo, hi, in) \
    asm("mov.b64 {%0, %1}, %2;" : "=f"(lo), "=f"(hi) : "l"(in))

// -------- device scratch (no allocs allowed; resolved in device code only) --------
__device__ float g_bufA[N_NODES * HID];   // ping
__device__ float g_bufB[N_NODES * HID];   // pong
__device__ float g_dis[N_NODES];          // rsqrt(deg) incl. self loop
__device__ int   g_ecnt[N_NODES];         // in-edge count (excl. self loop)
__device__ int   g_off[N_NODES + 1];      // CSR offsets (edges only)
__device__ int   g_cur[N_NODES];          // fill cursors
__device__ int   g_csr[E_EDGES];          // src node per dst-sorted edge
__device__ int   g_bsum[NBLK_SCAN];
__device__ float g_pool[G_GR * HID];
__device__ float g_cnt[G_GR];
__device__ int   g_is32;                  // 1 if index buffers are int32, 0 if int64

__device__ __forceinline__ float* buf_sel(int i) { return i ? g_bufB : g_bufA; }

__device__ __forceinline__ int load_idx(const void* p, long i) {
    return g_is32 ? ((const int*)p)[i] : (int)((const long long*)p)[i];
}

// -------- dtype probe: read first 2048 words of edge_index as int64 --------
__global__ void detect_kernel(const void* ei) {
    int t = threadIdx.x;
    if (t == 0) g_is32 = 0;
    __syncthreads();
    const long long* p = (const long long*)ei;
    for (int i = t; i < 2048; i += blockDim.x) {
        long long v = p[i];
        if (v < 0 || v >= N_NODES) g_is32 = 1;
    }
}

// -------- init --------
__global__ void init_kernel() {
    int i = blockIdx.x * blockDim.x + threadIdx.x;
    if (i < N_NODES) g_ecnt[i] = 0;
    if (i < G_GR * HID) g_pool[i] = 0.f;
    if (i < G_GR) g_cnt[i] = 0.f;
}

// -------- count in-degree over dst --------
__global__ void count_kernel(const void* __restrict__ ei) {
    int e = blockIdx.x * blockDim.x + threadIdx.x;
    if (e < E_EDGES) {
        int d = load_idx(ei, (long)E_EDGES + e);
        atomicAdd(&g_ecnt[d], 1);
    }
}

// -------- multi-block scan, phase A: per-block inclusive scan --------
__global__ __launch_bounds__(1024)
void scanA_kernel() {
    __shared__ int wsum[32];
    int t = threadIdx.x, b = blockIdx.x;
    int lane = t & 31, wid = t >> 5;
    int i = b * 1024 + t;
    int x = (i < N_NODES) ? g_ecnt[i] : 0;
    #pragma unroll
    for (int o = 1; o < 32; o <<= 1) {
        int y = __shfl_up_sync(0xffffffffu, x, o);
        if (lane >= o) x += y;
    }
    if (lane == 31) wsum[wid] = x;
    __syncthreads();
    if (wid == 0) {
        int s = wsum[lane];
        #pragma unroll
        for (int o = 1; o < 32; o <<= 1) {
            int y = __shfl_up_sync(0xffffffffu, s, o);
            if (lane >= o) s += y;
        }
        wsum[lane] = s;
    }
    __syncthreads();
    int incl = x + (wid > 0 ? wsum[wid - 1] : 0);
    if (i < N_NODES) g_off[i + 1] = incl;
    if (t == 1023) g_bsum[b] = incl;
}

// -------- phase B: exclusive scan of block totals (tiny) --------
__global__ void scanB_kernel() {
    if (threadIdx.x == 0) {
        int run = 0;
        for (int b = 0; b < NBLK_SCAN; b++) {
            int v = g_bsum[b];
            g_bsum[b] = run;
            run += v;
        }
    }
}

// -------- phase C: add carries; init dis/cur fused --------
__global__ __launch_bounds__(1024)
void scanC_kernel() {
    int i = blockIdx.x * 1024 + threadIdx.x;
    if (i < N_NODES) g_off[i + 1] += g_bsum[blockIdx.x];
    if (i == 0) g_off[0] = 0;
}

// -------- dis = rsqrt(deg incl self loop); cursor init --------
__global__ void dis_kernel() {
    int i = blockIdx.x * blockDim.x + threadIdx.x;
    if (i < N_NODES) {
        g_dis[i] = rsqrtf((float)(g_ecnt[i] + 1));
        g_cur[i] = g_off[i];
    }
}

// -------- fill CSR --------
__global__ void fill_kernel(const void* __restrict__ ei) {
    int e = blockIdx.x * blockDim.x + threadIdx.x;
    if (e < E_EDGES) {
        int s = load_idx(ei, e);
        int d = load_idx(ei, (long)E_EDGES + e);
        int pos = atomicAdd(&g_cur[d], 1);
        g_csr[pos] = s;
    }
}

// -------- SGEMM (f32x2 packed FMA): C[M,Nc] = A[M,K] @ B[K,Nc] --------
// BM=64 BN=128 BK=16; per thread 4x8 output via 4x4 packed f32x2 accumulators.
// A_ext != nullptr -> use it, else buf_sel(srcSel). C = buf_sel(dstSel).
__global__ __launch_bounds__(256)
void sgemm_kernel(const float* A_ext, int srcSel, int dstSel,
                  const float* __restrict__ B, int Nc, int K) {
    const int BM = 64, BN = 128, BK = 16;
    const float* A = A_ext ? A_ext : buf_sel(srcSel);
    float* C = buf_sel(dstSel);
    __shared__ float As[BK][BM];
    __shared__ float Bs[BK][BN];
    int tid = threadIdx.x;
    int tx = tid & 15, ty = tid >> 4;
    int row0 = blockIdx.y * BM, col0 = blockIdx.x * BN;

    unsigned long long acc2[4][4];
    #pragma unroll
    for (int m = 0; m < 4; m++)
        #pragma unroll
        for (int j = 0; j < 4; j++) acc2[m][j] = 0ULL;

    int arow = tid >> 2;          // 0..63
    int akq  = (tid & 3) * 4;     // k offset within BK (float4)
    int bk   = tid >> 4;          // 0..15
    int bn   = (tid & 15) * 4;    // 0..60

    for (int k0 = 0; k0 < K; k0 += BK) {
        float4 a4 = *(const float4*)(A + (long)(row0 + arow) * K + k0 + akq);
        As[akq + 0][arow] = a4.x;
        As[akq + 1][arow] = a4.y;
        As[akq + 2][arow] = a4.z;
        As[akq + 3][arow] = a4.w;
        float4 b4a = *(const float4*)(B + (long)(k0 + bk) * Nc + col0 + bn);
        float4 b4b = *(const float4*)(B + (long)(k0 + bk) * Nc + col0 + bn + 64);
        *(float4*)&Bs[bk][bn]      = b4a;
        *(float4*)&Bs[bk][bn + 64] = b4b;
        __syncthreads();
        #pragma unroll
        for (int k = 0; k < BK; k++) {
            float4 av = *(float4*)&As[k][ty * 4];      // 4 consecutive rows (m)
            unsigned long long ap[4];
            PACK_F32X2(ap[0], av.x, av.x);
            PACK_F32X2(ap[1], av.y, av.y);
            PACK_F32X2(ap[2], av.z, av.z);
            PACK_F32X2(ap[3], av.w, av.w);
            float4 t0 = *(float4*)&Bs[k][tx * 8];
            float4 t1 = *(float4*)&Bs[k][tx * 8 + 4];
            unsigned long long bp[4];
            bp[0] = ((unsigned long long*)&t0)[0];
            bp[1] = ((unsigned long long*)&t0)[1];
            bp[2] = ((unsigned long long*)&t1)[0];
            bp[3] = ((unsigned long long*)&t1)[1];
            #pragma unroll
            for (int m = 0; m < 4; m++)
                #pragma unroll
                for (int j = 0; j < 4; j++)
                    FMA_F32X2(acc2[m][j], ap[m], bp[j], acc2[m][j]);
        }
        __syncthreads();
    }
    #pragma unroll
    for (int m = 0; m < 4; m++) {
        long r = row0 + ty * 4 + m;
        float4 o0, o1;
        UNPACK_F32X2(o0.x, o0.y, acc2[m][0]);
        UNPACK_F32X2(o0.z, o0.w, acc2[m][1]);
        UNPACK_F32X2(o1.x, o1.y, acc2[m][2]);
        UNPACK_F32X2(o1.z, o1.w, acc2[m][3]);
        *(float4*)(C + r * Nc + col0 + tx * 8)     = o0;
        *(float4*)(C + r * Nc + col0 + tx * 8 + 4) = o1;
    }
}

// -------- aggregation: out = relu(self + sum_{e:dst=i} h[src]*dis[src]*dis[i] + b)
__global__ __launch_bounds__(256)
void agg_kernel(int srcSel, int dstSel, const float* __restrict__ bias) {
    const float* hin = buf_sel(srcSel);
    float* hout = buf_sel(dstSel);
    int node = blockIdx.x * 4 + (threadIdx.x >> 6);
    int t = threadIdx.x & 63;
    const float4* h4 = (const float4*)hin;
    float di = g_dis[node];
    float4 v = h4[(long)node * 64 + t];
    float w0 = di * di;
    float4 acc = make_float4(v.x * w0, v.y * w0, v.z * w0, v.w * w0);
    int e = g_off[node], end = g_off[node + 1];
    for (; e + 1 < end; e += 2) {
        int s0 = g_csr[e], s1 = g_csr[e + 1];
        float ws0 = g_dis[s0] * di, ws1 = g_dis[s1] * di;
        float4 u0 = h4[(long)s0 * 64 + t];
        float4 u1 = h4[(long)s1 * 64 + t];
        acc.x += u0.x * ws0 + u1.x * ws1;
        acc.y += u0.y * ws0 + u1.y * ws1;
        acc.z += u0.z * ws0 + u1.z * ws1;
        acc.w += u0.w * ws0 + u1.w * ws1;
    }
    if (e < end) {
        int s0 = g_csr[e];
        float ws0 = g_dis[s0] * di;
        float4 u0 = h4[(long)s0 * 64 + t];
        acc.x += u0.x * ws0; acc.y += u0.y * ws0;
        acc.z += u0.z * ws0; acc.w += u0.w * ws0;
    }
    float4 b = ((const float4*)bias)[t];
    float4 o;
    o.x = fmaxf(acc.x + b.x, 0.f);
    o.y = fmaxf(acc.y + b.y, 0.f);
    o.z = fmaxf(acc.z + b.z, 0.f);
    o.w = fmaxf(acc.w + b.w, 0.f);
    ((float4*)hout)[(long)node * 64 + t] = o;
}

// -------- mean pool --------
__global__ __launch_bounds__(256)
void pool_kernel(int srcSel, const void* __restrict__ batch) {
    const float* h = buf_sel(srcSel);
    int base = blockIdx.x * 32;
    int c = threadIdx.x;
    float acc = 0.f, cacc = 0.f;
    int gprev = load_idx(batch, base);
    for (int r = 0; r < 32; r++) {
        int i = base + r;
        int g = load_idx(batch, i);
        if (g != gprev) {
            atomicAdd(&g_pool[gprev * HID + c], acc);
            if (c == 0) atomicAdd(&g_cnt[gprev], cacc);
            acc = 0.f; cacc = 0.f; gprev = g;
        }
        acc += h[(long)i * HID + c];
        cacc += 1.f;
    }
    atomicAdd(&g_pool[gprev * HID + c], acc);
    if (c == 0) atomicAdd(&g_cnt[gprev], cacc);
}

// -------- final linear head --------
__global__ void final_kernel(const float* __restrict__ Wlin,
                             const float* __restrict__ blin,
                             float* __restrict__ out) {
    int t = threadIdx.x;
    if (t >= G_GR * OUT_CH) return;
    int g = t / OUT_CH, o = t % OUT_CH;
    float inv = 1.f / fmaxf(g_cnt[g], 1.f);
    float acc = 0.f;
    for (int c = 0; c < HID; c++)
        acc = fmaf(g_pool[g * HID + c] * inv, Wlin[c * OUT_CH + o], acc);
    out[t] = acc + blin[o];
}

extern "C" void kernel_launch(void* const* d_in, const int* in_sizes, int n_in,
                              void* d_out, int out_size) {
    const float* x     = (const float*)d_in[0];
    const void*  ei    = d_in[1];
    const void*  batch = d_in[2];
    const float* W1    = (const float*)d_in[3];
    const float* b1    = (const float*)d_in[4];
    const float* W2    = (const float*)d_in[5];
    const float* b2    = (const float*)d_in[6];
    const float* Wlin  = (const float*)d_in[7];
    const float* blin  = (const float*)d_in[8];
    float* out = (float*)d_out;

    // graph preprocessing
    detect_kernel<<<1, 256>>>(ei);
    init_kernel<<<(N_NODES + 255) / 256, 256>>>();
    count_kernel<<<(E_EDGES + 255) / 256, 256>>>(ei);
    scanA_kernel<<<NBLK_SCAN, 1024>>>();
    scanB_kernel<<<1, 32>>>();
    scanC_kernel<<<NBLK_SCAN, 1024>>>();
    dis_kernel<<<(N_NODES + 255) / 256, 256>>>();
    fill_kernel<<<(E_EDGES + 255) / 256, 256>>>(ei);

    // layer 1: h1 = x @ W1 -> bufA ; bufB = relu(agg(bufA) + b1)
    sgemm_kernel<<<dim3(HID / 128, N_NODES / 64), 256>>>(x, 0, 0, W1, HID, IN_CH);
    agg_kernel<<<N_NODES / 4, 256>>>(0, 1, b1);

    // layer 2: h2 = bufB @ W2 -> bufA ; bufB = relu(agg(bufA) + b2)
    sgemm_kernel<<<dim3(HID / 128, N_NODES / 64), 256>>>(nullptr, 1, 0, W2, HID, HID);
    agg_kernel<<<N_NODES / 4, 256>>>(0, 1, b2);

    // pool + head (reads bufB)
    pool_kernel<<<N_NODES / 32, 256>>>(1, batch);
    final_kernel<<<1, ((G_GR * OUT_CH + 31) / 32) * 32>>>(Wlin, blin, out);
}

// round 10
// speedup vs baseline: 1.2107x; 1.1605x over previous
#include <cuda_runtime.h>
#include <cstdint>

#define N_NODES 40000
#define E_EDGES 640000
#define IN_CH   128
#define HID     256
#define OUT_CH  10
#define G_GR    64
#define NBLK_SCAN 40   // ceil(40000/1024)

// packed 2-wide fp32 FMA (Blackwell f32x2 path; ptxas never auto-fuses this)
#define FMA_F32X2(d, a, b, c) \
    asm("fma.rn.f32x2 %0, %1, %2, %3;" : "=l"(d) : "l"(a), "l"(b), "l"(c))
#define PACK_F32X2(out, lo, hi) \
    asm("mov.b64 %0, {%1, %2};" : "=l"(out) : "f"(lo), "f"(hi))
#define UNPACK_F32X2(lo, hi, in) \
    asm("mov.b64 {%0, %1}, %2;" : "=f"(lo), "=f"(hi) : "l"(in))

#define CP_ASYNC16(dst_u32, src) \
    asm volatile("cp.async.ca.shared.global [%0], [%1], 16;" :: "r"(dst_u32), "l"(src))
#define CP_COMMIT() asm volatile("cp.async.commit_group;" ::: "memory")
#define CP_WAIT(n)  asm volatile("cp.async.wait_group %0;" :: "n"(n) : "memory")

__device__ __forceinline__ uint32_t smem_to_u32(const void* smem_ptr) {
    uint32_t addr;
    asm("{ .reg .u64 tmp; cvta.to.shared.u64 tmp, %1; cvt.u32.u64 %0, tmp; }"
        : "=r"(addr) : "l"(smem_ptr));
    return addr;
}

// -------- device scratch (no allocs allowed; resolved in device code only) --------
__device__ float g_bufA[N_NODES * HID];   // ping
__device__ float g_bufB[N_NODES * HID];   // pong
__device__ float g_dis[N_NODES];
__device__ int   g_ecnt[N_NODES];
__device__ int   g_off[N_NODES + 1];
__device__ int   g_cur[N_NODES];
__device__ int   g_csr[E_EDGES];
__device__ int   g_bsum[NBLK_SCAN];
__device__ float g_pool[G_GR * HID];
__device__ float g_cnt[G_GR];
__device__ int   g_is32;

__device__ __forceinline__ float* buf_sel(int i) { return i ? g_bufB : g_bufA; }

__device__ __forceinline__ int load_idx(const void* p, long i) {
    return g_is32 ? ((const int*)p)[i] : (int)((const long long*)p)[i];
}

// -------- dtype probe --------
__global__ void detect_kernel(const void* ei) {
    int t = threadIdx.x;
    if (t == 0) g_is32 = 0;
    __syncthreads();
    const long long* p = (const long long*)ei;
    for (int i = t; i < 2048; i += blockDim.x) {
        long long v = p[i];
        if (v < 0 || v >= N_NODES) g_is32 = 1;
    }
}

__global__ void init_kernel() {
    int i = blockIdx.x * blockDim.x + threadIdx.x;
    if (i < N_NODES) g_ecnt[i] = 0;
    if (i < G_GR * HID) g_pool[i] = 0.f;
    if (i < G_GR) g_cnt[i] = 0.f;
}

__global__ void count_kernel(const void* __restrict__ ei) {
    int e = blockIdx.x * blockDim.x + threadIdx.x;
    if (e < E_EDGES) {
        int d = load_idx(ei, (long)E_EDGES + e);
        atomicAdd(&g_ecnt[d], 1);
    }
}

__global__ __launch_bounds__(1024)
void scanA_kernel() {
    __shared__ int wsum[32];
    int t = threadIdx.x, b = blockIdx.x;
    int lane = t & 31, wid = t >> 5;
    int i = b * 1024 + t;
    int x = (i < N_NODES) ? g_ecnt[i] : 0;
    #pragma unroll
    for (int o = 1; o < 32; o <<= 1) {
        int y = __shfl_up_sync(0xffffffffu, x, o);
        if (lane >= o) x += y;
    }
    if (lane == 31) wsum[wid] = x;
    __syncthreads();
    if (wid == 0) {
        int s = wsum[lane];
        #pragma unroll
        for (int o = 1; o < 32; o <<= 1) {
            int y = __shfl_up_sync(0xffffffffu, s, o);
            if (lane >= o) s += y;
        }
        wsum[lane] = s;
    }
    __syncthreads();
    int incl = x + (wid > 0 ? wsum[wid - 1] : 0);
    if (i < N_NODES) g_off[i + 1] = incl;
    if (t == 1023) g_bsum[b] = incl;
}

__global__ void scanB_kernel() {
    if (threadIdx.x == 0) {
        int run = 0;
        for (int b = 0; b < NBLK_SCAN; b++) {
            int v = g_bsum[b];
            g_bsum[b] = run;
            run += v;
        }
    }
}

__global__ __launch_bounds__(1024)
void scanC_kernel() {
    int i = blockIdx.x * 1024 + threadIdx.x;
    if (i < N_NODES) g_off[i + 1] += g_bsum[blockIdx.x];
    if (i == 0) g_off[0] = 0;
}

__global__ void dis_kernel() {
    int i = blockIdx.x * blockDim.x + threadIdx.x;
    if (i < N_NODES) {
        g_dis[i] = rsqrtf((float)(g_ecnt[i] + 1));
        g_cur[i] = g_off[i];
    }
}

__global__ void fill_kernel(const void* __restrict__ ei) {
    int e = blockIdx.x * blockDim.x + threadIdx.x;
    if (e < E_EDGES) {
        int s = load_idx(ei, e);
        int d = load_idx(ei, (long)E_EDGES + e);
        int pos = atomicAdd(&g_cur[d], 1);
        g_csr[pos] = s;
    }
}

// -------- SGEMM v2: BM=128 BN=128 BK=16, 8x8/thread, cp.async 2-stage, f32x2 --------
// A_ext != nullptr -> use it, else buf_sel(srcSel). C = buf_sel(dstSel).
__global__ __launch_bounds__(256)
void sgemm_kernel(const float* A_ext, int srcSel, int dstSel,
                  const float* __restrict__ B, int Nc, int K) {
    const int BM = 128, BN = 128, BK = 16;
    const float* A = A_ext ? A_ext : buf_sel(srcSel);
    float* C = buf_sel(dstSel);

    __shared__ float As[2][BM * BK];   // [r][k] row-major: r*16+k
    __shared__ float Bs[2][BK * BN];   // [k][n]: k*128+n

    int tid = threadIdx.x;
    int tx = tid & 15;        // 0..15 -> n
    int ty = tid >> 4;        // 0..15 -> m
    int row0 = blockIdx.y * BM, col0 = blockIdx.x * BN;

    uint32_t asA = smem_to_u32(&As[0][0]);
    uint32_t asB = smem_to_u32(&Bs[0][0]);

    unsigned long long acc2[8][4];
    #pragma unroll
    for (int m = 0; m < 8; m++)
        #pragma unroll
        for (int j = 0; j < 4; j++) acc2[m][j] = 0ULL;

    // precompute per-thread load coords (2 chunks each for A and B)
    int ar[2], akq[2], bkk[2], bn4[2];
    #pragma unroll
    for (int h = 0; h < 2; h++) {
        int c = tid + h * 256;
        ar[h]  = c >> 2;            // 0..127
        akq[h] = (c & 3) * 4;       // 0,4,8,12
        bkk[h] = c >> 5;            // 0..15
        bn4[h] = (c & 31) * 4;      // 0..124
    }

    int nK = K / BK;

    // ---- issue tile kt into buffer bufi ----
    #define ISSUE_TILE(bufi, kt) do {                                          \
        int _k0 = (kt) * BK;                                                   \
        _Pragma("unroll")                                                      \
        for (int h = 0; h < 2; h++) {                                          \
            int _row = row0 + ar[h];                                           \
            if (_row >= N_NODES) _row = N_NODES - 1;                           \
            const float* _sa = A + (long)_row * K + _k0 + akq[h];              \
            uint32_t _da = asA + (uint32_t)((bufi) * BM * BK + ar[h] * BK + akq[h]) * 4u; \
            CP_ASYNC16(_da, _sa);                                              \
            const float* _sb = B + (long)(_k0 + bkk[h]) * Nc + col0 + bn4[h];  \
            uint32_t _db = asB + (uint32_t)((bufi) * BK * BN + bkk[h] * BN + bn4[h]) * 4u; \
            CP_ASYNC16(_db, _sb);                                              \
        }                                                                      \
        CP_COMMIT();                                                           \
    } while (0)

    ISSUE_TILE(0, 0);

    for (int kc = 0; kc < nK; kc++) {
        int cur = kc & 1;
        if (kc + 1 < nK) {
            ISSUE_TILE(1 - cur, kc + 1);
            CP_WAIT(1);
        } else {
            CP_WAIT(0);
        }
        __syncthreads();

        const float* sA = &As[cur][0];
        const float* sB = &Bs[cur][0];
        #pragma unroll
        for (int k = 0; k < BK; k++) {
            unsigned long long ap[8];
            #pragma unroll
            for (int i = 0; i < 8; i++) {
                float a = sA[(ty * 8 + i) * BK + k];
                PACK_F32X2(ap[i], a, a);
            }
            float4 t0 = *(const float4*)&sB[k * BN + tx * 8];
            float4 t1 = *(const float4*)&sB[k * BN + tx * 8 + 4];
            unsigned long long bp[4];
            bp[0] = ((const unsigned long long*)&t0)[0];
            bp[1] = ((const unsigned long long*)&t0)[1];
            bp[2] = ((const unsigned long long*)&t1)[0];
            bp[3] = ((const unsigned long long*)&t1)[1];
            #pragma unroll
            for (int m = 0; m < 8; m++)
                #pragma unroll
                for (int j = 0; j < 4; j++)
                    FMA_F32X2(acc2[m][j], ap[m], bp[j], acc2[m][j]);
        }
        __syncthreads();
    }
    #undef ISSUE_TILE

    #pragma unroll
    for (int m = 0; m < 8; m++) {
        long r = row0 + ty * 8 + m;
        if (r < N_NODES) {
            float4 o0, o1;
            UNPACK_F32X2(o0.x, o0.y, acc2[m][0]);
            UNPACK_F32X2(o0.z, o0.w, acc2[m][1]);
            UNPACK_F32X2(o1.x, o1.y, acc2[m][2]);
            UNPACK_F32X2(o1.z, o1.w, acc2[m][3]);
            *(float4*)(C + r * Nc + col0 + tx * 8)     = o0;
            *(float4*)(C + r * Nc + col0 + tx * 8 + 4) = o1;
        }
    }
}

// -------- aggregation --------
__global__ __launch_bounds__(256)
void agg_kernel(int srcSel, int dstSel, const float* __restrict__ bias) {
    const float* hin = buf_sel(srcSel);
    float* hout = buf_sel(dstSel);
    int node = blockIdx.x * 4 + (threadIdx.x >> 6);
    int t = threadIdx.x & 63;
    const float4* h4 = (const float4*)hin;
    float di = g_dis[node];
    float4 v = h4[(long)node * 64 + t];
    float w0 = di * di;
    float4 acc = make_float4(v.x * w0, v.y * w0, v.z * w0, v.w * w0);
    int e = g_off[node], end = g_off[node + 1];
    for (; e + 1 < end; e += 2) {
        int s0 = g_csr[e], s1 = g_csr[e + 1];
        float ws0 = g_dis[s0] * di, ws1 = g_dis[s1] * di;
        float4 u0 = h4[(long)s0 * 64 + t];
        float4 u1 = h4[(long)s1 * 64 + t];
        acc.x += u0.x * ws0 + u1.x * ws1;
        acc.y += u0.y * ws0 + u1.y * ws1;
        acc.z += u0.z * ws0 + u1.z * ws1;
        acc.w += u0.w * ws0 + u1.w * ws1;
    }
    if (e < end) {
        int s0 = g_csr[e];
        float ws0 = g_dis[s0] * di;
        float4 u0 = h4[(long)s0 * 64 + t];
        acc.x += u0.x * ws0; acc.y += u0.y * ws0;
        acc.z += u0.z * ws0; acc.w += u0.w * ws0;
    }
    float4 b = ((const float4*)bias)[t];
    float4 o;
    o.x = fmaxf(acc.x + b.x, 0.f);
    o.y = fmaxf(acc.y + b.y, 0.f);
    o.z = fmaxf(acc.z + b.z, 0.f);
    o.w = fmaxf(acc.w + b.w, 0.f);
    ((float4*)hout)[(long)node * 64 + t] = o;
}

// -------- mean pool --------
__global__ __launch_bounds__(256)
void pool_kernel(int srcSel, const void* __restrict__ batch) {
    const float* h = buf_sel(srcSel);
    int base = blockIdx.x * 32;
    int c = threadIdx.x;
    float acc = 0.f, cacc = 0.f;
    int gprev = load_idx(batch, base);
    for (int r = 0; r < 32; r++) {
        int i = base + r;
        int g = load_idx(batch, i);
        if (g != gprev) {
            atomicAdd(&g_pool[gprev * HID + c], acc);
            if (c == 0) atomicAdd(&g_cnt[gprev], cacc);
            acc = 0.f; cacc = 0.f; gprev = g;
        }
        acc += h[(long)i * HID + c];
        cacc += 1.f;
    }
    atomicAdd(&g_pool[gprev * HID + c], acc);
    if (c == 0) atomicAdd(&g_cnt[gprev], cacc);
}

// -------- final linear head --------
__global__ void final_kernel(const float* __restrict__ Wlin,
                             const float* __restrict__ blin,
                             float* __restrict__ out) {
    int t = threadIdx.x;
    if (t >= G_GR * OUT_CH) return;
    int g = t / OUT_CH, o = t % OUT_CH;
    float inv = 1.f / fmaxf(g_cnt[g], 1.f);
    float acc = 0.f;
    for (int c = 0; c < HID; c++)
        acc = fmaf(g_pool[g * HID + c] * inv, Wlin[c * OUT_CH + o], acc);
    out[t] = acc + blin[o];
}

extern "C" void kernel_launch(void* const* d_in, const int* in_sizes, int n_in,
                              void* d_out, int out_size) {
    const float* x     = (const float*)d_in[0];
    const void*  ei    = d_in[1];
    const void*  batch = d_in[2];
    const float* W1    = (const float*)d_in[3];
    const float* b1    = (const float*)d_in[4];
    const float* W2    = (const float*)d_in[5];
    const float* b2    = (const float*)d_in[6];
    const float* Wlin  = (const float*)d_in[7];
    const float* blin  = (const float*)d_in[8];
    float* out = (float*)d_out;

    const int nTilesM = (N_NODES + 127) / 128;  // 313

    // launches ordered so gemm #1 is launch index 5 (ncu -s 5 -c 1 profiles it)
    detect_kernel<<<1, 256>>>(ei);                           // 0
    init_kernel<<<(N_NODES + 255) / 256, 256>>>();           // 1
    count_kernel<<<(E_EDGES + 255) / 256, 256>>>(ei);        // 2
    scanA_kernel<<<NBLK_SCAN, 1024>>>();                     // 3
    scanB_kernel<<<1, 32>>>();                               // 4
    // layer-1 GEMM depends only on x/W1 — safe to hoist before CSR build
    sgemm_kernel<<<dim3(HID / 128, nTilesM), 256>>>(x, 0, 0, W1, HID, IN_CH);   // 5
    scanC_kernel<<<NBLK_SCAN, 1024>>>();                     // 6
    dis_kernel<<<(N_NODES + 255) / 256, 256>>>();            // 7
    fill_kernel<<<(E_EDGES + 255) / 256, 256>>>(ei);         // 8

    // layer 1 aggregation: bufB = relu(agg(bufA) + b1)
    agg_kernel<<<N_NODES / 4, 256>>>(0, 1, b1);

    // layer 2
    sgemm_kernel<<<dim3(HID / 128, nTilesM), 256>>>(nullptr, 1, 0, W2, HID, HID);
    agg_kernel<<<N_NODES / 4, 256>>>(0, 1, b2);

    // pool + head (reads bufB)
    pool_kernel<<<N_NODES / 32, 256>>>(1, batch);
    final_kernel<<<1, ((G_GR * OUT_CH + 31) / 32) * 32>>>(Wlin, blin, out);
}

// round 15
// speedup vs baseline: 1.3831x; 1.1424x over previous
#include <cuda_runtime.h>
#include <cstdint>

#define N_NODES 40000
#define E_EDGES 640000
#define IN_CH   128
#define HID     256
#define OUT_CH  10
#define G_GR    64
#define NBLK_SCAN 40   // ceil(40000/1024)

// packed 2-wide fp32 FMA
#define FMA_F32X2(d, a, b, c) \
    asm("fma.rn.f32x2 %0, %1, %2, %3;" : "=l"(d) : "l"(a), "l"(b), "l"(c))
#define PACK_F32X2(out, lo, hi) \
    asm("mov.b64 %0, {%1, %2};" : "=l"(out) : "f"(lo), "f"(hi))
#define UNPACK_F32X2(lo, hi, in) \
    asm("mov.b64 {%0, %1}, %2;" : "=f"(lo), "=f"(hi) : "l"(in))

#define CP_ASYNC16(dst_u32, src) \
    asm volatile("cp.async.ca.shared.global [%0], [%1], 16;" :: "r"(dst_u32), "l"(src))
#define CP_COMMIT() asm volatile("cp.async.commit_group;" ::: "memory")
#define CP_WAIT(n)  asm volatile("cp.async.wait_group %0;" :: "n"(n) : "memory")

__device__ __forceinline__ uint32_t smem_to_u32(const void* smem_ptr) {
    uint32_t addr;
    asm("{ .reg .u64 tmp; cvta.to.shared.u64 tmp, %1; cvt.u32.u64 %0, tmp; }"
        : "=r"(addr) : "l"(smem_ptr));
    return addr;
}

// -------- device scratch --------
__device__ float g_bufA[N_NODES * HID];   // ping
__device__ float g_bufB[N_NODES * HID];   // pong
__device__ float g_dis[N_NODES];
__device__ int   g_ecnt[N_NODES];
__device__ int   g_off[N_NODES + 1];
__device__ int   g_cur[N_NODES];
__device__ int   g_csr[E_EDGES];
__device__ int   g_bsum[NBLK_SCAN];
__device__ float g_pool[G_GR * HID];
__device__ float g_cnt[G_GR];
__device__ int   g_is32;

__device__ __forceinline__ float* buf_sel(int i) { return i ? g_bufB : g_bufA; }

__device__ __forceinline__ int load_idx(const void* p, long i) {
    return g_is32 ? ((const int*)p)[i] : (int)((const long long*)p)[i];
}

// -------- dtype probe --------
__global__ void detect_kernel(const void* ei) {
    int t = threadIdx.x;
    if (t == 0) g_is32 = 0;
    __syncthreads();
    const long long* p = (const long long*)ei;
    for (int i = t; i < 2048; i += blockDim.x) {
        long long v = p[i];
        if (v < 0 || v >= N_NODES) g_is32 = 1;
    }
}

__global__ void init_kernel() {
    int i = blockIdx.x * blockDim.x + threadIdx.x;
    if (i < N_NODES) g_ecnt[i] = 0;
    if (i < G_GR * HID) g_pool[i] = 0.f;
    if (i < G_GR) g_cnt[i] = 0.f;
}

__global__ void count_kernel(const void* __restrict__ ei) {
    int e = blockIdx.x * blockDim.x + threadIdx.x;
    if (e < E_EDGES) {
        int d = load_idx(ei, (long)E_EDGES + e);
        atomicAdd(&g_ecnt[d], 1);
    }
}

__global__ __launch_bounds__(1024)
void scanA_kernel() {
    __shared__ int wsum[32];
    int t = threadIdx.x, b = blockIdx.x;
    int lane = t & 31, wid = t >> 5;
    int i = b * 1024 + t;
    int x = (i < N_NODES) ? g_ecnt[i] : 0;
    #pragma unroll
    for (int o = 1; o < 32; o <<= 1) {
        int y = __shfl_up_sync(0xffffffffu, x, o);
        if (lane >= o) x += y;
    }
    if (lane == 31) wsum[wid] = x;
    __syncthreads();
    if (wid == 0) {
        int s = wsum[lane];
        #pragma unroll
        for (int o = 1; o < 32; o <<= 1) {
            int y = __shfl_up_sync(0xffffffffu, s, o);
            if (lane >= o) s += y;
        }
        wsum[lane] = s;
    }
    __syncthreads();
    int incl = x + (wid > 0 ? wsum[wid - 1] : 0);
    if (i < N_NODES) g_off[i + 1] = incl;
    if (t == 1023) g_bsum[b] = incl;
}

__global__ void scanB_kernel() {
    if (threadIdx.x == 0) {
        int run = 0;
        for (int b = 0; b < NBLK_SCAN; b++) {
            int v = g_bsum[b];
            g_bsum[b] = run;
            run += v;
        }
    }
}

__global__ __launch_bounds__(1024)
void scanC_kernel() {
    int i = blockIdx.x * 1024 + threadIdx.x;
    if (i < N_NODES) g_off[i + 1] += g_bsum[blockIdx.x];
    if (i == 0) g_off[0] = 0;
}

__global__ void dis_kernel() {
    int i = blockIdx.x * blockDim.x + threadIdx.x;
    if (i < N_NODES) {
        g_dis[i] = rsqrtf((float)(g_ecnt[i] + 1));
        g_cur[i] = g_off[i];
    }
}

__global__ void fill_kernel(const void* __restrict__ ei) {
    int e = blockIdx.x * blockDim.x + threadIdx.x;
    if (e < E_EDGES) {
        int s = load_idx(ei, e);
        int d = load_idx(ei, (long)E_EDGES + e);
        int pos = atomicAdd(&g_cur[d], 1);
        g_csr[pos] = s;
    }
}

// -------- SGEMM v3.1: BM=128 BN=128 BK=32, A smem transposed [k][m] pad 132
// (16B-aligned rows -> LDS.128 legal; 4-way STS conflict on transpose store
//  amortized over 1024 FFMA2/tile), B via cp.async 2-stage, f32x2 throughout.
#define APAD 132
#define AS_FLOATS (2 * 32 * APAD)
#define BS_FLOATS (2 * 32 * 128)
#define GEMM_SMEM_BYTES ((AS_FLOATS + BS_FLOATS) * 4)

__global__ __launch_bounds__(256, 2)
void sgemm_kernel(const float* A_ext, int srcSel, int dstSel,
                  const float* __restrict__ B, const float* __restrict__ bias,
                  int epi, int Nc, int K) {
    const int BM = 128, BK = 32;
    const float* A = A_ext ? A_ext : buf_sel(srcSel);
    float* C = buf_sel(dstSel);

    extern __shared__ float sm[];
    float* As = sm;                        // [2][32][APAD]
    float* Bs = sm + AS_FLOATS;            // [2][32][128]
    uint32_t bsAddr = smem_to_u32(Bs);

    int tid = threadIdx.x;
    int tx = tid & 15, ty = tid >> 4;
    int row0 = blockIdx.y * BM, col0 = blockIdx.x * 128;

    unsigned long long acc2[4][8];
    #pragma unroll
    for (int mp = 0; mp < 4; mp++)
        #pragma unroll
        for (int n = 0; n < 8; n++) acc2[mp][n] = 0ULL;

    // per-thread load coords (4 chunks of float4 each for A and B)
    int am[4], akq[4], bk[4], bn[4];
    #pragma unroll
    for (int h = 0; h < 4; h++) {
        int c = h * 256 + tid;
        am[h]  = c >> 3;           // 0..127
        akq[h] = (c & 7) * 4;      // 0..28
        bk[h]  = c >> 5;           // 0..31
        bn[h]  = (c & 31) * 4;     // 0..124
    }

    float4 aregs[2][4];
    int nK = K / BK;

    #define LDA(slot, kt) do {                                                 \
        int _k0 = (kt) * BK;                                                   \
        _Pragma("unroll")                                                      \
        for (int h = 0; h < 4; h++) {                                          \
            int _row = row0 + am[h];                                           \
            if (_row >= N_NODES) _row = N_NODES - 1;                           \
            aregs[slot][h] = *(const float4*)(A + (long)_row * K + _k0 + akq[h]); \
        }                                                                      \
    } while (0)

    #define LDB(bufi, kt) do {                                                 \
        int _k0 = (kt) * BK;                                                   \
        _Pragma("unroll")                                                      \
        for (int h = 0; h < 4; h++) {                                          \
            const float* _sb = B + (long)(_k0 + bk[h]) * Nc + col0 + bn[h];    \
            uint32_t _db = bsAddr + (uint32_t)((bufi) * 32 * 128 + bk[h] * 128 + bn[h]) * 4u; \
            CP_ASYNC16(_db, _sb);                                              \
        }                                                                      \
        CP_COMMIT();                                                           \
    } while (0)

    LDA(0, 0);
    LDB(0, 0);

    for (int kc = 0; kc < nK; kc++) {
        int cur = kc & 1;
        // store A regs -> transposed smem
        #pragma unroll
        for (int h = 0; h < 4; h++) {
            float* dst = As + cur * 32 * APAD + akq[h] * APAD + am[h];
            dst[0 * APAD] = aregs[cur][h].x;
            dst[1 * APAD] = aregs[cur][h].y;
            dst[2 * APAD] = aregs[cur][h].z;
            dst[3 * APAD] = aregs[cur][h].w;
        }
        if (kc + 1 < nK) {
            LDA(1 - cur, kc + 1);
            LDB(1 - cur, kc + 1);
            CP_WAIT(1);
        } else {
            CP_WAIT(0);
        }
        __syncthreads();

        const float* sA = As + cur * 32 * APAD;
        const float* sB = Bs + cur * 32 * 128;
        #pragma unroll
        for (int k = 0; k < BK; k++) {
            // A: 8 m-values (m-pairs native in u64), 16B-aligned rows
            float4 fa0 = *(const float4*)(sA + k * APAD + ty * 8);
            float4 fa1 = *(const float4*)(sA + k * APAD + ty * 8 + 4);
            unsigned long long ap[4];
            ap[0] = ((const unsigned long long*)&fa0)[0];
            ap[1] = ((const unsigned long long*)&fa0)[1];
            ap[2] = ((const unsigned long long*)&fa1)[0];
            ap[3] = ((const unsigned long long*)&fa1)[1];
            // B: 8 n-values broadcast-packed
            float4 t0 = *(const float4*)(sB + k * 128 + tx * 8);
            float4 t1 = *(const float4*)(sB + k * 128 + tx * 8 + 4);
            unsigned long long bp[8];
            PACK_F32X2(bp[0], t0.x, t0.x); PACK_F32X2(bp[1], t0.y, t0.y);
            PACK_F32X2(bp[2], t0.z, t0.z); PACK_F32X2(bp[3], t0.w, t0.w);
            PACK_F32X2(bp[4], t1.x, t1.x); PACK_F32X2(bp[5], t1.y, t1.y);
            PACK_F32X2(bp[6], t1.z, t1.z); PACK_F32X2(bp[7], t1.w, t1.w);
            #pragma unroll
            for (int mp = 0; mp < 4; mp++)
                #pragma unroll
                for (int n = 0; n < 8; n++)
                    FMA_F32X2(acc2[mp][n], ap[mp], bp[n], acc2[mp][n]);
        }
        __syncthreads();
    }
    #undef LDA
    #undef LDB

    // epilogue (optional bias+relu)
    float bv[8];
    if (epi) {
        float4 q0 = *(const float4*)(bias + col0 + tx * 8);
        float4 q1 = *(const float4*)(bias + col0 + tx * 8 + 4);
        bv[0] = q0.x; bv[1] = q0.y; bv[2] = q0.z; bv[3] = q0.w;
        bv[4] = q1.x; bv[5] = q1.y; bv[6] = q1.z; bv[7] = q1.w;
    }
    #pragma unroll
    for (int mp = 0; mp < 4; mp++) {
        float lo[8], hi[8];
        #pragma unroll
        for (int n = 0; n < 8; n++) UNPACK_F32X2(lo[n], hi[n], acc2[mp][n]);
        if (epi) {
            #pragma unroll
            for (int n = 0; n < 8; n++) {
                lo[n] = fmaxf(lo[n] + bv[n], 0.f);
                hi[n] = fmaxf(hi[n] + bv[n], 0.f);
            }
        }
        long r0 = row0 + ty * 8 + 2 * mp;
        if (r0 < N_NODES) {
            *(float4*)(C + r0 * Nc + col0 + tx * 8)     = make_float4(lo[0], lo[1], lo[2], lo[3]);
            *(float4*)(C + r0 * Nc + col0 + tx * 8 + 4) = make_float4(lo[4], lo[5], lo[6], lo[7]);
        }
        if (r0 + 1 < N_NODES) {
            *(float4*)(C + (r0 + 1) * Nc + col0 + tx * 8)     = make_float4(hi[0], hi[1], hi[2], hi[3]);
            *(float4*)(C + (r0 + 1) * Nc + col0 + tx * 8 + 4) = make_float4(hi[4], hi[5], hi[6], hi[7]);
        }
    }
}

// -------- aggregation (width-parametric) --------
__global__ __launch_bounds__(256)
void agg_kernel(const float* hin_ext, int srcSel, int dstSel,
                const float* bias, int w4) {
    const float* hin = hin_ext ? hin_ext : buf_sel(srcSel);
    float* hout = buf_sel(dstSel);
    int npb = 256 / w4;
    int grp = threadIdx.x / w4;
    int node = blockIdx.x * npb + grp;
    int t = threadIdx.x - grp * w4;
    const float4* h4 = (const float4*)hin;
    float di = g_dis[node];
    float4 v = h4[(long)node * w4 + t];
    float w0 = di * di;
    float4 acc = make_float4(v.x * w0, v.y * w0, v.z * w0, v.w * w0);
    int e = g_off[node], end = g_off[node + 1];
    for (; e + 1 < end; e += 2) {
        int s0 = g_csr[e], s1 = g_csr[e + 1];
        float ws0 = g_dis[s0] * di, ws1 = g_dis[s1] * di;
        float4 u0 = h4[(long)s0 * w4 + t];
        float4 u1 = h4[(long)s1 * w4 + t];
        acc.x += u0.x * ws0 + u1.x * ws1;
        acc.y += u0.y * ws0 + u1.y * ws1;
        acc.z += u0.z * ws0 + u1.z * ws1;
        acc.w += u0.w * ws0 + u1.w * ws1;
    }
    if (e < end) {
        int s0 = g_csr[e];
        float ws0 = g_dis[s0] * di;
        float4 u0 = h4[(long)s0 * w4 + t];
        acc.x += u0.x * ws0; acc.y += u0.y * ws0;
        acc.z += u0.z * ws0; acc.w += u0.w * ws0;
    }
    float4 o = acc;
    if (bias) {
        float4 b = ((const float4*)bias)[t];
        o.x = fmaxf(acc.x + b.x, 0.f);
        o.y = fmaxf(acc.y + b.y, 0.f);
        o.z = fmaxf(acc.z + b.z, 0.f);
        o.w = fmaxf(acc.w + b.w, 0.f);
    }
    ((float4*)hout)[(long)node * w4 + t] = o;
}

// -------- mean pool --------
__global__ __launch_bounds__(256)
void pool_kernel(int srcSel, const void* __restrict__ batch) {
    const float* h = buf_sel(srcSel);
    int base = blockIdx.x * 32;
    int c = threadIdx.x;
    float acc = 0.f, cacc = 0.f;
    int gprev = load_idx(batch, base);
    for (int r = 0; r < 32; r++) {
        int i = base + r;
        int g = load_idx(batch, i);
        if (g != gprev) {
            atomicAdd(&g_pool[gprev * HID + c], acc);
            if (c == 0) atomicAdd(&g_cnt[gprev], cacc);
            acc = 0.f; cacc = 0.f; gprev = g;
        }
        acc += h[(long)i * HID + c];
        cacc += 1.f;
    }
    atomicAdd(&g_pool[gprev * HID + c], acc);
    if (c == 0) atomicAdd(&g_cnt[gprev], cacc);
}

// -------- final linear head --------
__global__ void final_kernel(const float* __restrict__ Wlin,
                             const float* __restrict__ blin,
                             float* __restrict__ out) {
    int t = threadIdx.x;
    if (t >= G_GR * OUT_CH) return;
    int g = t / OUT_CH, o = t % OUT_CH;
    float inv = 1.f / fmaxf(g_cnt[g], 1.f);
    float acc = 0.f;
    for (int c = 0; c < HID; c++)
        acc = fmaf(g_pool[g * HID + c] * inv, Wlin[c * OUT_CH + o], acc);
    out[t] = acc + blin[o];
}

extern "C" void kernel_launch(void* const* d_in, const int* in_sizes, int n_in,
                              void* d_out, int out_size) {
    const float* x     = (const float*)d_in[0];
    const void*  ei    = d_in[1];
    const void*  batch = d_in[2];
    const float* W1    = (const float*)d_in[3];
    const float* b1    = (const float*)d_in[4];
    const float* W2    = (const float*)d_in[5];
    const float* b2    = (const float*)d_in[6];
    const float* Wlin  = (const float*)d_in[7];
    const float* blin  = (const float*)d_in[8];
    float* out = (float*)d_out;

    cudaFuncSetAttribute(sgemm_kernel,
                         cudaFuncAttributeMaxDynamicSharedMemorySize, GEMM_SMEM_BYTES);

    const int nTilesM = (N_NODES + 127) / 128;  // 313

    // graph preprocessing
    detect_kernel<<<1, 256>>>(ei);
    init_kernel<<<(N_NODES + 255) / 256, 256>>>();
    count_kernel<<<(E_EDGES + 255) / 256, 256>>>(ei);
    scanA_kernel<<<NBLK_SCAN, 1024>>>();
    scanB_kernel<<<1, 32>>>();
    scanC_kernel<<<NBLK_SCAN, 1024>>>();
    dis_kernel<<<(N_NODES + 255) / 256, 256>>>();
    fill_kernel<<<(E_EDGES + 255) / 256, 256>>>(ei);

    // layer 1 (commuted): bufB[:,0:128] = agg(x); bufA = relu(aggX @ W1 + b1)
    agg_kernel<<<N_NODES / 8, 256>>>(x, 0, 1, nullptr, 32);
    sgemm_kernel<<<dim3(2, nTilesM), 256, GEMM_SMEM_BYTES>>>(
        nullptr, 1, 0, W1, b1, 1, HID, IN_CH);

    // layer 2: bufB = bufA @ W2 ; bufA = relu(agg(bufB) + b2)
    sgemm_kernel<<<dim3(2, nTilesM), 256, GEMM_SMEM_BYTES>>>(
        nullptr, 0, 1, W2, nullptr, 0, HID, HID);
    agg_kernel<<<N_NODES / 4, 256>>>(nullptr, 1, 0, b2, 64);

    // pool + head (reads bufA)
    pool_kernel<<<N_NODES / 32, 256>>>(0, batch);
    final_kernel<<<1, ((G_GR * OUT_CH + 31) / 32) * 32>>>(Wlin, blin, out);
}